// round 1
// baseline (speedup 1.0000x reference)
#include <cuda_runtime.h>
#include <cstdint>

// ---------------------------------------------------------------------------
// Reading_memory: B=65536, L=5, H=100 fused pipeline, fp32 with f32x2 packing.
//   K1: mem_4att = tanh(memory @ W_mem + b_mem)
//   K2: sub_4att = tanh(cat(sub_emb, raw) @ W_sub + b_sub)
//   K3: att = softmax(sub_4att @ mem_4att^T) (row-masked), sub_mem = att @ memory
//   K4: g = sigmoid(cat(sub_emb, sub_mem, sub_mem*sub_emb) @ W_gate + b_gate)
//       out = (1-g)*sub_emb + g*sub_mem
// ---------------------------------------------------------------------------

#define B_MAX 65536
typedef unsigned long long ull;

__device__ __align__(16) static float g_m4[B_MAX * 500];
__device__ __align__(16) static float g_s4[B_MAX * 500];
__device__ __align__(16) static float g_sm[B_MAX * 500];

__device__ __forceinline__ ull fma2(ull a, ull b, ull c) {
    ull d;
    asm("fma.rn.f32x2 %0, %1, %2, %3;" : "=l"(d) : "l"(a), "l"(b), "l"(c));
    return d;
}
__device__ __forceinline__ ull pack2(float lo, float hi) {
    ull r;
    asm("mov.b64 %0, {%1, %2};" : "=l"(r) : "r"(__float_as_uint(lo)), "r"(__float_as_uint(hi)));
    return r;
}
__device__ __forceinline__ float2 unpack2(ull v) {
    unsigned int lo, hi;
    asm("mov.b64 {%0, %1}, %2;" : "=r"(lo), "=r"(hi) : "l"(v));
    float2 r; r.x = __uint_as_float(lo); r.y = __uint_as_float(hi);
    return r;
}
__device__ __forceinline__ float sigf(float x) {
    return 1.0f / (1.0f + __expf(-x));
}

// ---------------------------------------------------------------------------
// GEMM kernel: per batch, Y[q][n] = act( sum_k X[q][k] * W[k][n] + bias[n] )
//   MODE 0: X = memory            (K=100), Y = tanh -> g_m4
//   MODE 1: X = cat(sub_emb, raw) (K=200), Y = tanh -> g_s4
//   MODE 2: X = cat(sub_emb, sub_mem, sub_mem*sub_emb) (K=300),
//           g = sigmoid, out = se + g*(sm - se)
// Layout: 256 threads = 10 groups of 25; each thread: 2 batches x 4 cols x 5 q.
// x staged duplicated (v,v) as f32x2; W staged raw; K streamed in 50-chunks.
// ---------------------------------------------------------------------------

#define NBATCH 20
#define GROUPS 10
#define TPG 25
#define KCHUNK 50
#define XELEMS (NBATCH * 5 * KCHUNK)   // 5000 ull = 40000 B
#define WELEMS (KCHUNK * 100)          // 5000 f  = 20000 B
#define SMEM_BYTES (XELEMS * 8 + WELEMS * 4)

template <int MODE>
__global__ __launch_bounds__(256)
void gemm_kernel(const float* __restrict__ sub_emb,
                 const float* __restrict__ memory,
                 const float* __restrict__ raw,
                 const float* __restrict__ W,
                 const float* __restrict__ bias,
                 float* __restrict__ dout,
                 int B)
{
    constexpr int KTOT = (MODE == 0) ? 100 : (MODE == 1 ? 200 : 300);
    extern __shared__ __align__(16) char smraw[];
    ull*   xbuf = (ull*)smraw;
    float* wbuf = (float*)(smraw + XELEMS * 8);

    const int tid = threadIdx.x;
    const int b0  = blockIdx.x * NBATCH;
    const bool active = tid < GROUPS * TPG;
    const int g  = tid / TPG;
    const int t  = tid % TPG;
    const int c0 = 4 * t;

    // accumulators [q][batch-in-pair][col-pair], initialized with bias
    ull acc[5][2][2];
    {
        ull b01 = 0, b23 = 0;
        if (active) {
            float4 bv = *(const float4*)&bias[c0];
            b01 = pack2(bv.x, bv.y);
            b23 = pack2(bv.z, bv.w);
        }
#pragma unroll
        for (int q = 0; q < 5; q++)
#pragma unroll
            for (int bb = 0; bb < 2; bb++) {
                acc[q][bb][0] = b01;
                acc[q][bb][1] = b23;
            }
    }

    for (int k0 = 0; k0 < KTOT; k0 += KCHUNK) {
        __syncthreads();
        // ---- stage x (duplicated) ----
        for (int idx = tid; idx < XELEMS; idx += 256) {
            int bb  = idx / (5 * KCHUNK);
            int rem = idx - bb * (5 * KCHUNK);
            int q   = rem / KCHUNK;
            int kk  = rem - q * KCHUNK;
            int b   = b0 + bb;
            float v = 0.0f;
            if (b < B) {
                int k = k0 + kk;
                const int base = (b * 5 + q) * 100;
                if (MODE == 0) {
                    v = memory[base + k];
                } else if (MODE == 1) {
                    v = (k < 100) ? sub_emb[base + k] : raw[base + k - 100];
                } else {
                    if (k < 100)      v = sub_emb[base + k];
                    else if (k < 200) v = g_sm[base + k - 100];
                    else              v = sub_emb[base + k - 200] * g_sm[base + k - 200];
                }
            }
            xbuf[idx] = pack2(v, v);
        }
        // ---- stage W chunk (rows k0..k0+49 are contiguous) ----
        for (int idx = tid; idx < WELEMS; idx += 256) {
            wbuf[idx] = W[k0 * 100 + idx];
        }
        __syncthreads();

        if (active) {
            const ulonglong2* xv = (const ulonglong2*)xbuf;
            const int r0 = (2 * g)     * 5 * (KCHUNK / 2);
            const int r1 = (2 * g + 1) * 5 * (KCHUNK / 2);
#pragma unroll 5
            for (int i = 0; i < KCHUNK / 2; i++) {
                const int kk = 2 * i;
                ulonglong2 w0 = *(const ulonglong2*)&wbuf[kk * 100 + c0];
                ulonglong2 w1 = *(const ulonglong2*)&wbuf[(kk + 1) * 100 + c0];
#pragma unroll
                for (int q = 0; q < 5; q++) {
                    ulonglong2 x0 = xv[r0 + q * (KCHUNK / 2) + i];
                    ulonglong2 x1 = xv[r1 + q * (KCHUNK / 2) + i];
                    acc[q][0][0] = fma2(x0.x, w0.x, acc[q][0][0]);
                    acc[q][0][1] = fma2(x0.x, w0.y, acc[q][0][1]);
                    acc[q][0][0] = fma2(x0.y, w1.x, acc[q][0][0]);
                    acc[q][0][1] = fma2(x0.y, w1.y, acc[q][0][1]);
                    acc[q][1][0] = fma2(x1.x, w0.x, acc[q][1][0]);
                    acc[q][1][1] = fma2(x1.x, w0.y, acc[q][1][1]);
                    acc[q][1][0] = fma2(x1.y, w1.x, acc[q][1][0]);
                    acc[q][1][1] = fma2(x1.y, w1.y, acc[q][1][1]);
                }
            }
        }
    }

    // ---- epilogue ----
    if (active) {
        float* outp = (MODE == 0) ? g_m4 : (MODE == 1) ? g_s4 : dout;
#pragma unroll
        for (int bb = 0; bb < 2; bb++) {
            int b = b0 + 2 * g + bb;
            if (b >= B) continue;
#pragma unroll
            for (int q = 0; q < 5; q++) {
                float2 a01 = unpack2(acc[q][bb][0]);
                float2 a23 = unpack2(acc[q][bb][1]);
                float z0 = a01.x, z1 = a01.y, z2 = a23.x, z3 = a23.y;
                const int off = (b * 5 + q) * 100 + c0;
                if (MODE < 2) {
                    float4 y;
                    y.x = tanhf(z0); y.y = tanhf(z1);
                    y.z = tanhf(z2); y.w = tanhf(z3);
                    *(float4*)&outp[off] = y;
                } else {
                    float4 se = *(const float4*)&sub_emb[off];
                    float4 sm = *(const float4*)&g_sm[off];
                    float4 o;
                    o.x = fmaf(sigf(z0), sm.x - se.x, se.x);
                    o.y = fmaf(sigf(z1), sm.y - se.y, se.y);
                    o.z = fmaf(sigf(z2), sm.z - se.z, se.z);
                    o.w = fmaf(sigf(z3), sm.w - se.w, se.w);
                    *(float4*)&outp[off] = o;
                }
            }
        }
    }
}

// ---------------------------------------------------------------------------
// Attention kernel: one warp per batch, 8 batches per CTA.
//   att[q][k] = <s4[q], m4[k]>; row-softmax; invalid rows (q >= len) -> 0
//   sub_mem[q][n] = sum_k att[q][k] * memory[b][k][n]  -> g_sm
// (inf_mask adds the same constant to every key of an invalid row, so softmax
//  is unchanged; zero_mask then zeroes the row -> sub_mem row = 0.)
// ---------------------------------------------------------------------------
__global__ __launch_bounds__(256)
void attn_kernel(const float* __restrict__ memory,
                 const int* __restrict__ sub_len,
                 int B)
{
    __shared__ __align__(16) float s4s[8][500];
    __shared__ __align__(16) float m4s[8][500];
    __shared__ float atts[8][25];
    __shared__ __align__(16) ull attd[8][25];

    const int w    = threadIdx.x >> 5;
    const int lane = threadIdx.x & 31;
    const int b    = blockIdx.x * 8 + w;
    if (b >= B) return;

    for (int i = lane; i < 125; i += 32) {
        *(float4*)&s4s[w][4 * i] = *(const float4*)&g_s4[b * 500 + 4 * i];
        *(float4*)&m4s[w][4 * i] = *(const float4*)&g_m4[b * 500 + 4 * i];
    }
    __syncwarp();

    if (lane < 25) {
        const int q = lane / 5, kk = lane % 5;
        float a = 0.0f;
#pragma unroll 4
        for (int h = 0; h < 100; h++)
            a += s4s[w][q * 100 + h] * m4s[w][kk * 100 + h];
        atts[w][lane] = a;
    }
    __syncwarp();

    if (lane < 5) {
        const int q = lane;
        const int len = sub_len[b];
        float a[5];
#pragma unroll
        for (int i = 0; i < 5; i++) a[i] = atts[w][q * 5 + i];
        float m = a[0];
#pragma unroll
        for (int i = 1; i < 5; i++) m = fmaxf(m, a[i]);
        float e[5], s = 0.0f;
#pragma unroll
        for (int i = 0; i < 5; i++) { e[i] = __expf(a[i] - m); s += e[i]; }
        const float inv = (q < len) ? (1.0f / s) : 0.0f;
#pragma unroll
        for (int i = 0; i < 5; i++) {
            float r = e[i] * inv;
            attd[w][q * 5 + i] = pack2(r, r);
        }
    }
    __syncwarp();

    if (lane < 25) {
        const int c0 = 4 * lane;
        ull acc[5][2];
#pragma unroll
        for (int q = 0; q < 5; q++) { acc[q][0] = 0ull; acc[q][1] = 0ull; }
#pragma unroll
        for (int kk = 0; kk < 5; kk++) {
            ulonglong2 mv = *(const ulonglong2*)&memory[b * 500 + kk * 100 + c0];
#pragma unroll
            for (int q = 0; q < 5; q++) {
                ull ad = attd[w][q * 5 + kk];
                acc[q][0] = fma2(ad, mv.x, acc[q][0]);
                acc[q][1] = fma2(ad, mv.y, acc[q][1]);
            }
        }
#pragma unroll
        for (int q = 0; q < 5; q++) {
            float2 a01 = unpack2(acc[q][0]);
            float2 a23 = unpack2(acc[q][1]);
            float4 o; o.x = a01.x; o.y = a01.y; o.z = a23.x; o.w = a23.y;
            *(float4*)&g_sm[b * 500 + q * 100 + c0] = o;
        }
    }
}

// ---------------------------------------------------------------------------
extern "C" void kernel_launch(void* const* d_in, const int* in_sizes, int n_in,
                              void* d_out, int out_size)
{
    const float* sub_emb = (const float*)d_in[0];
    const float* memory  = (const float*)d_in[1];
    const int*   sub_len = (const int*)d_in[2];
    const float* raw     = (const float*)d_in[3];
    const float* W_mem   = (const float*)d_in[4];
    const float* b_mem   = (const float*)d_in[5];
    const float* W_sub   = (const float*)d_in[6];
    const float* b_sub   = (const float*)d_in[7];
    const float* W_gate  = (const float*)d_in[8];
    const float* b_gate  = (const float*)d_in[9];
    float* out = (float*)d_out;
    const int B = in_sizes[2];

    cudaFuncSetAttribute(gemm_kernel<0>, cudaFuncAttributeMaxDynamicSharedMemorySize, SMEM_BYTES);
    cudaFuncSetAttribute(gemm_kernel<1>, cudaFuncAttributeMaxDynamicSharedMemorySize, SMEM_BYTES);
    cudaFuncSetAttribute(gemm_kernel<2>, cudaFuncAttributeMaxDynamicSharedMemorySize, SMEM_BYTES);

    const int nc = (B + NBATCH - 1) / NBATCH;
    gemm_kernel<0><<<nc, 256, SMEM_BYTES>>>(sub_emb, memory, raw, W_mem, b_mem, nullptr, B);
    gemm_kernel<1><<<nc, 256, SMEM_BYTES>>>(sub_emb, memory, raw, W_sub, b_sub, nullptr, B);
    attn_kernel<<<(B + 7) / 8, 256>>>(memory, sub_len, B);
    gemm_kernel<2><<<nc, 256, SMEM_BYTES>>>(sub_emb, memory, raw, W_gate, b_gate, out, B);
}

// round 2
// speedup vs baseline: 1.3738x; 1.3738x over previous
#include <cuda_runtime.h>
#include <cstdint>

// ---------------------------------------------------------------------------
// Fully fused Reading_memory: B=65536, L=5, H=100.
// One CTA = 20 batches resident in smem; weights streamed per 50-k chunk.
//   stage1: m4 = tanh(mem @ W_mem + b)          (K=100)
//   stage2: s4 = tanh(cat(se,raw) @ W_sub + b)  (K=200)
//   attn  : att=softmax(s4 m4^T) masked; sm = att @ mem (sm overwrites mem)
//   stage4: g = sigmoid(cat(se,sm,se*sm) @ W_gate + b); out = se + g*(sm-se)
// f32x2 packed FMA throughout; column-pair packing, x duplicated per chunk.
// ---------------------------------------------------------------------------

typedef unsigned long long ull;

#define NB 20           // batches per CTA
#define NG 10           // batch-pair groups (2 batches each)
#define TQ 25           // column-quads (4 cols each -> 100)
#define KC 50           // k-chunk
#define THREADS 256

struct __align__(16) SM {
    float se[NB * 500];     // sub_emb (live whole kernel)
    float rs[NB * 500];     // raw -> s4
    float ms[NB * 500];     // memory -> sub_mem
    float m4[NB * 500];     // mem_4att
    ull   xd[NB * 5 * KC];  // duplicated x chunk: [bq][k]
    float ws[KC * 100];     // weight chunk (natural)
    float att[NB * 25];     // attention scores
};
#define SMEM_BYTES ((int)sizeof(SM))

__device__ __forceinline__ ull fma2(ull a, ull b, ull c) {
    ull d;
    asm("fma.rn.f32x2 %0, %1, %2, %3;" : "=l"(d) : "l"(a), "l"(b), "l"(c));
    return d;
}
__device__ __forceinline__ ull pack2(float lo, float hi) {
    ull r;
    asm("mov.b64 %0, {%1, %2};" : "=l"(r) : "r"(__float_as_uint(lo)), "r"(__float_as_uint(hi)));
    return r;
}
__device__ __forceinline__ float2 unpack2(ull v) {
    unsigned int lo, hi;
    asm("mov.b64 {%0, %1}, %2;" : "=r"(lo), "=r"(hi) : "l"(v));
    float2 r; r.x = __uint_as_float(lo); r.y = __uint_as_float(hi);
    return r;
}
__device__ __forceinline__ float sigf(float x) { return 1.0f / (1.0f + __expf(-x)); }

// ---- W chunk prefetch: 5000 floats = 1250 float4 across 256 threads ----
__device__ __forceinline__ void ldw(float4 w[5], const float* __restrict__ W, int k0) {
#pragma unroll
    for (int i = 0; i < 5; i++) {
        int idx = threadIdx.x + i * THREADS;
        if (idx < 1250) w[i] = *(const float4*)(W + k0 * 100 + idx * 4);
    }
}
__device__ __forceinline__ void stw(SM* s, const float4 w[5]) {
#pragma unroll
    for (int i = 0; i < 5; i++) {
        int idx = threadIdx.x + i * THREADS;
        if (idx < 1250) *(float4*)&s->ws[idx * 4] = w[i];
    }
}

// ---- stage duplicated-x chunk from resident smem arrays ----
template <int MODE>
__device__ __forceinline__ void stx(SM* s, int k0) {
#pragma unroll
    for (int ii = 0; ii < (NB * 5 * KC + THREADS - 1) / THREADS; ii++) {
        int idx = threadIdx.x + ii * THREADS;
        if (idx < NB * 5 * KC) {
            int bq = idx / KC;
            int gk = k0 + (idx - bq * KC);
            float v;
            if (MODE == 0) {
                v = s->ms[bq * 100 + gk];
            } else if (MODE == 1) {
                v = (gk < 100) ? s->se[bq * 100 + gk] : s->rs[bq * 100 + gk - 100];
            } else {
                if (gk < 100)      v = s->se[bq * 100 + gk];
                else if (gk < 200) v = s->ms[bq * 100 + gk - 100];
                else               v = s->se[bq * 100 + gk - 200] * s->ms[bq * 100 + gk - 200];
            }
            s->xd[idx] = pack2(v, v);
        }
    }
}

// ---- one GEMM stage ----
template <int MODE>
__device__ __forceinline__ void gemm_stage(SM* s,
                                           const float* __restrict__ W,
                                           const float* __restrict__ bias,
                                           float* __restrict__ dout,
                                           int b0, int B)
{
    constexpr int KT = (MODE == 0) ? 100 : (MODE == 1 ? 200 : 300);
    constexpr int NC = KT / KC;
    const int tid = threadIdx.x;
    const bool act = tid < NG * TQ;
    const int g = tid / TQ;         // batch-pair group (warp-major -> 1-2 distinct/warp)
    const int t = tid - g * TQ;     // column quad
    const int c0 = 4 * t;

    ull a[5][2][2];
    {
        ull b01 = 0, b23 = 0;
        if (act) {
            float4 bv = *(const float4*)&bias[c0];
            b01 = pack2(bv.x, bv.y);
            b23 = pack2(bv.z, bv.w);
        }
#pragma unroll
        for (int q = 0; q < 5; q++)
#pragma unroll
            for (int bb = 0; bb < 2; bb++) { a[q][bb][0] = b01; a[q][bb][1] = b23; }
    }

    float4 wreg[5];
    ldw(wreg, W, 0);

    for (int c = 0; c < NC; c++) {
        __syncthreads();                 // prior math / phase done
        stw(s, wreg);
        stx<MODE>(s, c * KC);
        __syncthreads();
        if (c + 1 < NC) ldw(wreg, W, (c + 1) * KC);   // overlap with math

        if (act) {
            const ull* xdA = &s->xd[((2 * g) * 5) * KC];
            const ull* xdB = &s->xd[((2 * g + 1) * 5) * KC];
#pragma unroll
            for (int i = 0; i < KC / 2; i++) {
                const int k = 2 * i;
                ulonglong2 w0 = *(const ulonglong2*)&s->ws[k * 100 + c0];
                ulonglong2 w1 = *(const ulonglong2*)&s->ws[(k + 1) * 100 + c0];
#pragma unroll
                for (int q = 0; q < 5; q++) {
                    ulonglong2 x0 = *(const ulonglong2*)&xdA[q * KC + k];
                    ulonglong2 x1 = *(const ulonglong2*)&xdB[q * KC + k];
                    a[q][0][0] = fma2(x0.x, w0.x, a[q][0][0]);
                    a[q][0][1] = fma2(x0.x, w0.y, a[q][0][1]);
                    a[q][0][0] = fma2(x0.y, w1.x, a[q][0][0]);
                    a[q][0][1] = fma2(x0.y, w1.y, a[q][0][1]);
                    a[q][1][0] = fma2(x1.x, w0.x, a[q][1][0]);
                    a[q][1][1] = fma2(x1.x, w0.y, a[q][1][1]);
                    a[q][1][0] = fma2(x1.y, w1.x, a[q][1][0]);
                    a[q][1][1] = fma2(x1.y, w1.y, a[q][1][1]);
                }
            }
        }
    }

    if (act) {
#pragma unroll
        for (int bb = 0; bb < 2; bb++) {
            const int b = 2 * g + bb;
#pragma unroll
            for (int q = 0; q < 5; q++) {
                float2 a01 = unpack2(a[q][bb][0]);
                float2 a23 = unpack2(a[q][bb][1]);
                const int off = b * 500 + q * 100 + c0;
                if (MODE < 2) {
                    float4 y;
                    y.x = tanhf(a01.x); y.y = tanhf(a01.y);
                    y.z = tanhf(a23.x); y.w = tanhf(a23.y);
                    float* dst = (MODE == 0) ? s->m4 : s->rs;
                    *(float4*)&dst[off] = y;
                } else {
                    const int gb = b0 + b;
                    if (gb < B) {
                        float4 sev = *(const float4*)&s->se[off];
                        float4 smv = *(const float4*)&s->ms[off];
                        float4 o;
                        o.x = fmaf(sigf(a01.x), smv.x - sev.x, sev.x);
                        o.y = fmaf(sigf(a01.y), smv.y - sev.y, sev.y);
                        o.z = fmaf(sigf(a23.x), smv.z - sev.z, sev.z);
                        o.w = fmaf(sigf(a23.y), smv.w - sev.w, sev.w);
                        *(float4*)&dout[gb * 500 + q * 100 + c0] = o;
                    }
                }
            }
        }
    }
}

// ---------------------------------------------------------------------------
__global__ __launch_bounds__(THREADS, 1)
void fused_kernel(const float* __restrict__ sub_emb,
                  const float* __restrict__ memory,
                  const int*   __restrict__ sub_len,
                  const float* __restrict__ raw,
                  const float* __restrict__ W_mem,  const float* __restrict__ b_mem,
                  const float* __restrict__ W_sub,  const float* __restrict__ b_sub,
                  const float* __restrict__ W_gate, const float* __restrict__ b_gate,
                  float* __restrict__ dout, int B)
{
    extern __shared__ __align__(16) char smraw[];
    SM* s = (SM*)smraw;
    const int tid = threadIdx.x;
    const int b0 = blockIdx.x * NB;

    // ---- stage resident inputs (coalesced float4, conflict-free STS) ----
    {
        const float4 z4 = make_float4(0.f, 0.f, 0.f, 0.f);
#pragma unroll
        for (int ii = 0; ii < (NB * 125 + THREADS - 1) / THREADS; ii++) {
            int idx = tid + ii * THREADS;            // float4 index, 2500 total
            if (idx < NB * 125) {
                int b = idx / 125, r = idx - b * 125;
                int gb = b0 + b;
                float4 v0 = z4, v1 = z4, v2 = z4;
                if (gb < B) {
                    v0 = *(const float4*)&sub_emb[gb * 500 + 4 * r];
                    v1 = *(const float4*)&raw[gb * 500 + 4 * r];
                    v2 = *(const float4*)&memory[gb * 500 + 4 * r];
                }
                *(float4*)&s->se[b * 500 + 4 * r] = v0;
                *(float4*)&s->rs[b * 500 + 4 * r] = v1;
                *(float4*)&s->ms[b * 500 + 4 * r] = v2;
            }
        }
    }
    // (gemm_stage starts with __syncthreads before touching xd/ws)

    gemm_stage<0>(s, W_mem, b_mem, nullptr, b0, B);   // -> m4
    gemm_stage<1>(s, W_sub, b_sub, nullptr, b0, B);   // -> rs(=s4)
    __syncthreads();                                  // m4/s4 visible

    // ---- attention scores: att[b][q][kv] = <s4[q], m4[kv]> ----
    if (tid < NG * TQ) {
        const int g2 = tid / TQ;
        const int qk = tid - g2 * TQ;
        const int q = qk / 5, kv = qk - 5 * q;
#pragma unroll
        for (int bb = 0; bb < 2; bb++) {
            const int b = 2 * g2 + bb;
            ull acc2 = 0ull;
#pragma unroll
            for (int j = 0; j < 25; j++) {
                ulonglong2 sv = *(const ulonglong2*)&s->rs[b * 500 + q * 100 + 4 * j];
                ulonglong2 mv = *(const ulonglong2*)&s->m4[b * 500 + kv * 100 + 4 * j];
                acc2 = fma2(sv.x, mv.x, acc2);
                acc2 = fma2(sv.y, mv.y, acc2);
            }
            float2 f = unpack2(acc2);
            s->att[b * 25 + q * 5 + kv] = f.x + f.y;
        }
    }
    __syncthreads();

    // ---- softmax per (b,q) with length mask ----
    if (tid < NB * 5) {
        const int b = tid / 5, q = tid - 5 * b;
        const int gb = b0 + b;
        const int len = (gb < B) ? sub_len[gb] : 5;
        float v[5];
#pragma unroll
        for (int kv = 0; kv < 5; kv++) v[kv] = s->att[b * 25 + q * 5 + kv];
        float m = v[0];
#pragma unroll
        for (int kv = 1; kv < 5; kv++) m = fmaxf(m, v[kv]);
        float e[5], sm = 0.f;
#pragma unroll
        for (int kv = 0; kv < 5; kv++) { e[kv] = __expf(v[kv] - m); sm += e[kv]; }
        const float inv = (q < len) ? (1.0f / sm) : 0.0f;
#pragma unroll
        for (int kv = 0; kv < 5; kv++) s->att[b * 25 + q * 5 + kv] = e[kv] * inv;
    }
    __syncthreads();

    // ---- sub_mem = att @ memory  (writes overwrite ms; per-thread safe) ----
    if (tid < NG * TQ) {
        const int g = tid / TQ;
        const int t = tid - g * TQ;
        const int c0 = 4 * t;
#pragma unroll
        for (int bb = 0; bb < 2; bb++) {
            const int b = 2 * g + bb;
            float av[25];
#pragma unroll
            for (int j = 0; j < 25; j++) av[j] = s->att[b * 25 + j];
            ull c2[5][2];
#pragma unroll
            for (int q = 0; q < 5; q++) { c2[q][0] = 0ull; c2[q][1] = 0ull; }
#pragma unroll
            for (int kv = 0; kv < 5; kv++) {
                ulonglong2 mv = *(const ulonglong2*)&s->ms[b * 500 + kv * 100 + c0];
#pragma unroll
                for (int q = 0; q < 5; q++) {
                    ull ap = pack2(av[q * 5 + kv], av[q * 5 + kv]);
                    c2[q][0] = fma2(ap, mv.x, c2[q][0]);
                    c2[q][1] = fma2(ap, mv.y, c2[q][1]);
                }
            }
#pragma unroll
            for (int q = 0; q < 5; q++) {
                float2 a01 = unpack2(c2[q][0]);
                float2 a23 = unpack2(c2[q][1]);
                float4 o; o.x = a01.x; o.y = a01.y; o.z = a23.x; o.w = a23.y;
                *(float4*)&s->ms[b * 500 + q * 100 + c0] = o;
            }
        }
    }
    // gemm_stage<2> begins with __syncthreads

    gemm_stage<2>(s, W_gate, b_gate, dout, b0, B);    // -> gmem out
}

// ---------------------------------------------------------------------------
extern "C" void kernel_launch(void* const* d_in, const int* in_sizes, int n_in,
                              void* d_out, int out_size)
{
    const float* sub_emb = (const float*)d_in[0];
    const float* memory  = (const float*)d_in[1];
    const int*   sub_len = (const int*)d_in[2];
    const float* raw     = (const float*)d_in[3];
    const float* W_mem   = (const float*)d_in[4];
    const float* b_mem   = (const float*)d_in[5];
    const float* W_sub   = (const float*)d_in[6];
    const float* b_sub   = (const float*)d_in[7];
    const float* W_gate  = (const float*)d_in[8];
    const float* b_gate  = (const float*)d_in[9];
    float* out = (float*)d_out;
    const int B = in_sizes[2];

    cudaFuncSetAttribute(fused_kernel, cudaFuncAttributeMaxDynamicSharedMemorySize, SMEM_BYTES);
    const int nc = (B + NB - 1) / NB;
    fused_kernel<<<nc, THREADS, SMEM_BYTES>>>(sub_emb, memory, sub_len, raw,
                                              W_mem, b_mem, W_sub, b_sub,
                                              W_gate, b_gate, out, B);
}

// round 3
// speedup vs baseline: 1.9761x; 1.4384x over previous
#include <cuda_runtime.h>
#include <cstdint>

// ---------------------------------------------------------------------------
// Fused Reading_memory, R3: B=65536, L=5, H=100.
// NB=10 batches/CTA, 128 threads, ~99KB smem -> 2 CTAs/SM.
// x read directly from resident smem (LDS.64 + mov dup); w staged via cp.async.
// ---------------------------------------------------------------------------

typedef unsigned long long ull;

#define NB 10           // batches per CTA
#define NG 5            // batch-pair groups (2 batches each)
#define TQ 25           // column-quads
#define KC 50           // k-chunk
#define THREADS 128

struct __align__(16) SM {
    float se[NB * 500];   // sub_emb (live whole kernel)
    float rs[NB * 500];   // raw -> s4
    float ms[NB * 500];   // memory -> sub_mem
    float m4[NB * 500];   // mem_4att
    float ws[KC * 100];   // weight chunk
    float att[NB * 25];   // attention scores
};
#define SMEM_BYTES ((int)sizeof(SM))

__device__ __forceinline__ ull fma2(ull a, ull b, ull c) {
    ull d;
    asm("fma.rn.f32x2 %0, %1, %2, %3;" : "=l"(d) : "l"(a), "l"(b), "l"(c));
    return d;
}
__device__ __forceinline__ ull pack2(float lo, float hi) {
    ull r;
    asm("mov.b64 %0, {%1, %2};" : "=l"(r) : "r"(__float_as_uint(lo)), "r"(__float_as_uint(hi)));
    return r;
}
__device__ __forceinline__ float2 unpack2(ull v) {
    unsigned int lo, hi;
    asm("mov.b64 {%0, %1}, %2;" : "=r"(lo), "=r"(hi) : "l"(v));
    float2 r; r.x = __uint_as_float(lo); r.y = __uint_as_float(hi);
    return r;
}
__device__ __forceinline__ float sigf(float x) { return 1.0f / (1.0f + __expf(-x)); }

__device__ __forceinline__ void cpa16(void* dst_smem, const void* src) {
    unsigned saddr = (unsigned)__cvta_generic_to_shared(dst_smem);
    asm volatile("cp.async.cg.shared.global [%0], [%1], 16;" :: "r"(saddr), "l"(src));
}
__device__ __forceinline__ void cpa_commit_wait() {
    asm volatile("cp.async.commit_group;");
    asm volatile("cp.async.wait_group 0;" ::: "memory");
}

// ---- core MMA over one 50-k chunk; x read straight from smem ----
template <bool PROD>
__device__ __forceinline__ void mm(const float* __restrict__ xarr,
                                   const float* __restrict__ parr,
                                   const float* __restrict__ ws,
                                   ull a[5][2][2], int g, int c0)
{
    const float* xb0 = xarr + (2 * g) * 500;
    const float* xb1 = xarr + (2 * g + 1) * 500;
    const float* pb0 = PROD ? parr + (2 * g) * 500 : nullptr;
    const float* pb1 = PROD ? parr + (2 * g + 1) * 500 : nullptr;
#pragma unroll
    for (int i = 0; i < KC / 2; i++) {
        const int k = 2 * i;
        ulonglong2 w0 = *(const ulonglong2*)&ws[k * 100 + c0];
        ulonglong2 w1 = *(const ulonglong2*)&ws[(k + 1) * 100 + c0];
#pragma unroll
        for (int q = 0; q < 5; q++) {
            float2 x0 = *(const float2*)&xb0[q * 100 + k];
            float2 x1 = *(const float2*)&xb1[q * 100 + k];
            if (PROD) {
                float2 p0 = *(const float2*)&pb0[q * 100 + k];
                float2 p1 = *(const float2*)&pb1[q * 100 + k];
                x0.x *= p0.x; x0.y *= p0.y;
                x1.x *= p1.x; x1.y *= p1.y;
            }
            ull xa0 = pack2(x0.x, x0.x), xb0d = pack2(x0.y, x0.y);
            ull xa1 = pack2(x1.x, x1.x), xb1d = pack2(x1.y, x1.y);
            a[q][0][0] = fma2(xa0, w0.x, a[q][0][0]);
            a[q][0][1] = fma2(xa0, w0.y, a[q][0][1]);
            a[q][0][0] = fma2(xb0d, w1.x, a[q][0][0]);
            a[q][0][1] = fma2(xb0d, w1.y, a[q][0][1]);
            a[q][1][0] = fma2(xa1, w0.x, a[q][1][0]);
            a[q][1][1] = fma2(xa1, w0.y, a[q][1][1]);
            a[q][1][0] = fma2(xb1d, w1.x, a[q][1][0]);
            a[q][1][1] = fma2(xb1d, w1.y, a[q][1][1]);
        }
    }
}

// ---- one GEMM stage ----
template <int MODE>
__device__ __forceinline__ void gemm_stage(SM* s,
                                           const float* __restrict__ W,
                                           const float* __restrict__ bias,
                                           float* __restrict__ dout,
                                           int b0, int B)
{
    constexpr int NC = (MODE == 0) ? 2 : (MODE == 1 ? 4 : 6);
    const int tid = threadIdx.x;
    const bool act = tid < NG * TQ;
    const int g = tid / TQ;
    const int t = tid - g * TQ;
    const int c0 = 4 * t;

    ull a[5][2][2];
    {
        ull b01 = 0, b23 = 0;
        if (act) {
            float4 bv = *(const float4*)&bias[c0];
            b01 = pack2(bv.x, bv.y);
            b23 = pack2(bv.z, bv.w);
        }
#pragma unroll
        for (int q = 0; q < 5; q++)
#pragma unroll
            for (int bb = 0; bb < 2; bb++) { a[q][bb][0] = b01; a[q][bb][1] = b23; }
    }

    for (int c = 0; c < NC; c++) {
        __syncthreads();            // prior math done reading ws
        {
            const float4* wsrc = (const float4*)(W + c * KC * 100);
#pragma unroll
            for (int i = 0; i < 10; i++) {
                int idx = tid + i * THREADS;
                if (idx < 1250) cpa16(&s->ws[idx * 4], wsrc + idx);
            }
            cpa_commit_wait();
        }
        __syncthreads();

        if (act) {
            const int koff = (c & 1) * KC;
            if (MODE == 0) {
                mm<false>(s->ms + koff, nullptr, s->ws, a, g, c0);
            } else if (MODE == 1) {
                mm<false>((c < 2 ? s->se : s->rs) + koff, nullptr, s->ws, a, g, c0);
            } else {
                if (c < 2)      mm<false>(s->se + koff, nullptr, s->ws, a, g, c0);
                else if (c < 4) mm<false>(s->ms + koff, nullptr, s->ws, a, g, c0);
                else            mm<true>(s->se + koff, s->ms + koff, s->ws, a, g, c0);
            }
        }
    }

    if (MODE < 2) __syncthreads();  // math done before overwriting rs (MODE1 reads rs)

    if (act) {
#pragma unroll
        for (int bb = 0; bb < 2; bb++) {
            const int b = 2 * g + bb;
#pragma unroll
            for (int q = 0; q < 5; q++) {
                float2 a01 = unpack2(a[q][bb][0]);
                float2 a23 = unpack2(a[q][bb][1]);
                const int off = b * 500 + q * 100 + c0;
                if (MODE < 2) {
                    float4 y;
                    y.x = tanhf(a01.x); y.y = tanhf(a01.y);
                    y.z = tanhf(a23.x); y.w = tanhf(a23.y);
                    float* dst = (MODE == 0) ? s->m4 : s->rs;
                    *(float4*)&dst[off] = y;
                } else {
                    const int gb = b0 + b;
                    if (gb < B) {
                        float4 sev = *(const float4*)&s->se[off];
                        float4 smv = *(const float4*)&s->ms[off];
                        float4 o;
                        o.x = fmaf(sigf(a01.x), smv.x - sev.x, sev.x);
                        o.y = fmaf(sigf(a01.y), smv.y - sev.y, sev.y);
                        o.z = fmaf(sigf(a23.x), smv.z - sev.z, sev.z);
                        o.w = fmaf(sigf(a23.y), smv.w - sev.w, sev.w);
                        *(float4*)&dout[gb * 500 + q * 100 + c0] = o;
                    }
                }
            }
        }
    }
}

// ---------------------------------------------------------------------------
__global__ __launch_bounds__(THREADS, 2)
void fused_kernel(const float* __restrict__ sub_emb,
                  const float* __restrict__ memory,
                  const int*   __restrict__ sub_len,
                  const float* __restrict__ raw,
                  const float* __restrict__ W_mem,  const float* __restrict__ b_mem,
                  const float* __restrict__ W_sub,  const float* __restrict__ b_sub,
                  const float* __restrict__ W_gate, const float* __restrict__ b_gate,
                  float* __restrict__ dout, int B)
{
    extern __shared__ __align__(16) char smraw[];
    SM* s = (SM*)smraw;
    const int tid = threadIdx.x;
    const int b0 = blockIdx.x * NB;

    // ---- stage resident inputs via cp.async (1250 float4 per array) ----
    {
        const float4 z4 = make_float4(0.f, 0.f, 0.f, 0.f);
#pragma unroll
        for (int i = 0; i < 10; i++) {
            int idx = tid + i * THREADS;            // float4 index
            if (idx < NB * 125) {
                int b = idx / 125, r = idx - b * 125;
                int gb = b0 + b;
                if (gb < B) {
                    cpa16(&s->se[b * 500 + 4 * r], &sub_emb[gb * 500 + 4 * r]);
                    cpa16(&s->rs[b * 500 + 4 * r], &raw[gb * 500 + 4 * r]);
                    cpa16(&s->ms[b * 500 + 4 * r], &memory[gb * 500 + 4 * r]);
                } else {
                    *(float4*)&s->se[b * 500 + 4 * r] = z4;
                    *(float4*)&s->rs[b * 500 + 4 * r] = z4;
                    *(float4*)&s->ms[b * 500 + 4 * r] = z4;
                }
            }
        }
        cpa_commit_wait();
        __syncthreads();
    }

    gemm_stage<0>(s, W_mem, b_mem, nullptr, b0, B);   // -> m4
    gemm_stage<1>(s, W_sub, b_sub, nullptr, b0, B);   // -> rs(=s4)
    __syncthreads();                                  // m4/s4 visible

    // ---- attention scores: att[b][q][kv] = <s4[q], m4[kv]> ----
    if (tid < NG * TQ) {
        const int g2 = tid / TQ;
        const int qk = tid - g2 * TQ;
        const int q = qk / 5, kv = qk - 5 * q;
#pragma unroll
        for (int bb = 0; bb < 2; bb++) {
            const int b = 2 * g2 + bb;
            ull acc2 = 0ull;
#pragma unroll
            for (int j = 0; j < 25; j++) {
                ulonglong2 sv = *(const ulonglong2*)&s->rs[b * 500 + q * 100 + 4 * j];
                ulonglong2 mv = *(const ulonglong2*)&s->m4[b * 500 + kv * 100 + 4 * j];
                acc2 = fma2(sv.x, mv.x, acc2);
                acc2 = fma2(sv.y, mv.y, acc2);
            }
            float2 f = unpack2(acc2);
            s->att[b * 25 + q * 5 + kv] = f.x + f.y;
        }
    }
    __syncthreads();

    // ---- softmax per (b,q) with length mask ----
    if (tid < NB * 5) {
        const int b = tid / 5, q = tid - 5 * b;
        const int gb = b0 + b;
        const int len = (gb < B) ? sub_len[gb] : 5;
        float v[5];
#pragma unroll
        for (int kv = 0; kv < 5; kv++) v[kv] = s->att[b * 25 + q * 5 + kv];
        float m = v[0];
#pragma unroll
        for (int kv = 1; kv < 5; kv++) m = fmaxf(m, v[kv]);
        float e[5], sm = 0.f;
#pragma unroll
        for (int kv = 0; kv < 5; kv++) { e[kv] = __expf(v[kv] - m); sm += e[kv]; }
        const float inv = (q < len) ? (1.0f / sm) : 0.0f;
#pragma unroll
        for (int kv = 0; kv < 5; kv++) s->att[b * 25 + q * 5 + kv] = e[kv] * inv;
    }
    __syncthreads();

    // ---- sub_mem = att @ memory (overwrites ms; column-partitioned, safe) ----
    if (tid < NG * TQ) {
        const int g = tid / TQ;
        const int t = tid - g * TQ;
        const int c0 = 4 * t;
#pragma unroll
        for (int bb = 0; bb < 2; bb++) {
            const int b = 2 * g + bb;
            float av[25];
#pragma unroll
            for (int j = 0; j < 25; j++) av[j] = s->att[b * 25 + j];
            ull c2[5][2];
#pragma unroll
            for (int q = 0; q < 5; q++) { c2[q][0] = 0ull; c2[q][1] = 0ull; }
#pragma unroll
            for (int kv = 0; kv < 5; kv++) {
                ulonglong2 mv = *(const ulonglong2*)&s->ms[b * 500 + kv * 100 + c0];
#pragma unroll
                for (int q = 0; q < 5; q++) {
                    ull ap = pack2(av[q * 5 + kv], av[q * 5 + kv]);
                    c2[q][0] = fma2(ap, mv.x, c2[q][0]);
                    c2[q][1] = fma2(ap, mv.y, c2[q][1]);
                }
            }
#pragma unroll
            for (int q = 0; q < 5; q++) {
                float2 a01 = unpack2(c2[q][0]);
                float2 a23 = unpack2(c2[q][1]);
                float4 o; o.x = a01.x; o.y = a01.y; o.z = a23.x; o.w = a23.y;
                *(float4*)&s->ms[b * 500 + q * 100 + c0] = o;
            }
        }
    }
    // gemm_stage<2> begins with __syncthreads

    gemm_stage<2>(s, W_gate, b_gate, dout, b0, B);    // -> gmem out
}

// ---------------------------------------------------------------------------
extern "C" void kernel_launch(void* const* d_in, const int* in_sizes, int n_in,
                              void* d_out, int out_size)
{
    const float* sub_emb = (const float*)d_in[0];
    const float* memory  = (const float*)d_in[1];
    const int*   sub_len = (const int*)d_in[2];
    const float* raw     = (const float*)d_in[3];
    const float* W_mem   = (const float*)d_in[4];
    const float* b_mem   = (const float*)d_in[5];
    const float* W_sub   = (const float*)d_in[6];
    const float* b_sub   = (const float*)d_in[7];
    const float* W_gate  = (const float*)d_in[8];
    const float* b_gate  = (const float*)d_in[9];
    float* out = (float*)d_out;
    const int B = in_sizes[2];

    cudaFuncSetAttribute(fused_kernel, cudaFuncAttributeMaxDynamicSharedMemorySize, SMEM_BYTES);
    const int nc = (B + NB - 1) / NB;
    fused_kernel<<<nc, THREADS, SMEM_BYTES>>>(sub_emb, memory, sub_len, raw,
                                              W_mem, b_mem, W_sub, b_sub,
                                              W_gate, b_gate, out, B);
}